// round 8
// baseline (speedup 1.0000x reference)
#include <cuda_runtime.h>
#include <cuda_bf16.h>
#include <cstdint>

// Inputs (metadata order):
//   d_in[0] = x      float32 [262144]  (1 MB; first 57344 elems smem-resident)
//   d_in[1] = A_vals float32 [NNZ]
//   d_in[2] = A_rows int32   [NNZ]
//   d_in[3] = A_cols int32   [NNZ]
// Output: float32 [262144]
//
// R8: persistent CTAs (148 x 1024 thr), each holding x[0:57344) (224KB) in
// smem. 21.9% of the uniform-random gathers are served by the smem crossbar
// instead of L1tex/L2 sector reads -> relieves both binding pipes (L2 86%,
// L1 80%). Streams + RED scatter unchanged.

#define XS_N       57344                  // floats of x cached in smem (224KB)
#define XS_BYTES   (XS_N * 4)
#define CTA_THREADS 1024
#define GRID_CTAS   148

__global__ void __launch_bounds__(CTA_THREADS, 1) coo_spmv_smemx_kernel(
    const float*  __restrict__ x,
    const float4* __restrict__ vals4,
    const int4*   __restrict__ rows4,
    const int4*   __restrict__ cols4,
    float*        __restrict__ out,
    int nnz4, int nnz)
{
    extern __shared__ float xs[];   // XS_N floats

    // Stage x[0:XS_N) into smem, coalesced float4 (14 iters/thread).
    {
        const float4* src = (const float4*)x;
        float4* dst = (float4*)xs;
        #pragma unroll
        for (int j = 0; j < XS_N / 4 / CTA_THREADS; j++)
            dst[threadIdx.x + j * CTA_THREADS] = src[threadIdx.x + j * CTA_THREADS];
    }
    __syncthreads();

    const int tid    = blockIdx.x * CTA_THREADS + threadIdx.x;
    const int stride = GRID_CTAS * CTA_THREADS;

    for (int i = tid; i < nnz4; i += stride) {
        float4 v = __ldg(&vals4[i]);
        int4   r = __ldg(&rows4[i]);
        int4   c = __ldg(&cols4[i]);

        float x0 = (c.x < XS_N) ? xs[c.x] : __ldg(&x[c.x]);
        float x1 = (c.y < XS_N) ? xs[c.y] : __ldg(&x[c.y]);
        float x2 = (c.z < XS_N) ? xs[c.z] : __ldg(&x[c.z]);
        float x3 = (c.w < XS_N) ? xs[c.w] : __ldg(&x[c.w]);

        atomicAdd(&out[r.x], v.x * x0);
        atomicAdd(&out[r.y], v.y * x1);
        atomicAdd(&out[r.z], v.z * x2);
        atomicAdd(&out[r.w], v.w * x3);
    }

    // Scalar tail (nnz % 4) — empty for this shape, kept correct.
    for (int i = nnz4 * 4 + tid; i < nnz; i += stride) {
        const float* vs = (const float*)vals4;
        const int*   rs = (const int*)rows4;
        const int*   cs = (const int*)cols4;
        int cc = cs[i];
        float xv = (cc < XS_N) ? xs[cc] : __ldg(&x[cc]);
        atomicAdd(&out[rs[i]], vs[i] * xv);
    }
}

extern "C" void kernel_launch(void* const* d_in, const int* in_sizes, int n_in,
                              void* d_out, int out_size) {
    const float* x    = (const float*)d_in[0];
    const float* vals = (const float*)d_in[1];
    const int*   rows = (const int*)d_in[2];
    const int*   cols = (const int*)d_in[3];
    float* out = (float*)d_out;

    const int nnz  = in_sizes[1];
    const int nnz4 = nnz / 4;

    // Opt-in to 224KB dynamic smem (idempotent, graph-capturable host call).
    cudaFuncSetAttribute(coo_spmv_smemx_kernel,
                         cudaFuncAttributeMaxDynamicSharedMemorySize, XS_BYTES);

    // Zero-init output (harness poisons it).
    cudaMemsetAsync(out, 0, (size_t)out_size * sizeof(float), 0);

    coo_spmv_smemx_kernel<<<GRID_CTAS, CTA_THREADS, XS_BYTES>>>(
        x, (const float4*)vals, (const int4*)rows, (const int4*)cols,
        out, nnz4, nnz);
}

// round 9
// speedup vs baseline: 1.2233x; 1.2233x over previous
#include <cuda_runtime.h>
#include <cuda_bf16.h>
#include <cstdint>

// Inputs (metadata order):
//   d_in[0] = x      float32 [262144]  (1 MB, random-gathered, L2-resident)
//   d_in[1] = A_vals float32 [NNZ]     (streamed once)
//   d_in[2] = A_rows int32   [NNZ]     (streamed once)
//   d_in[3] = A_cols int32   [NNZ]     (streamed once)
// Output: float32 [262144]
//
// Unsorted-COO SpMV at the co-saturated LSU/L1tex + LTS floor (~135K cyc/SM:
// 8.39M divergent gather wavefronts + 8.39M spread RED lanes + 100MB stream).
// Falsified alternatives: L1 cache-policy hints (R2/R3/R5 neutral), DSMEM
// cluster gather (R4, 3x worse), TMA-staged streams (R7 neutral), smem x-slice
// (R8, 38% worse via occupancy collapse). This is the best-measured shape:
// 4 nnz/thread, 256-thr blocks, 8192 CTAs, ~84% occupancy.

__global__ void zero_out_kernel(float4* __restrict__ out, int n4) {
    int i = blockIdx.x * blockDim.x + threadIdx.x;
    if (i < n4) out[i] = make_float4(0.f, 0.f, 0.f, 0.f);
}

__global__ void __launch_bounds__(256) coo_spmv_kernel(
    const float*  __restrict__ x,
    const float4* __restrict__ vals4,
    const int4*   __restrict__ rows4,
    const int4*   __restrict__ cols4,
    float*        __restrict__ out,
    int nnz4)
{
    int i = blockIdx.x * blockDim.x + threadIdx.x;
    if (i >= nnz4) return;

    // Three independent 16B streaming loads -> MLP 3 per thread.
    float4 v = __ldg(&vals4[i]);
    int4   r = __ldg(&rows4[i]);
    int4   c = __ldg(&cols4[i]);

    // Random gathers from L2-resident x (1 MB).
    float x0 = __ldg(&x[c.x]);
    float x1 = __ldg(&x[c.y]);
    float x2 = __ldg(&x[c.z]);
    float x3 = __ldg(&x[c.w]);

    // Scatter-add: return value unused -> RED.E.ADD.F32 at L2.
    atomicAdd(&out[r.x], v.x * x0);
    atomicAdd(&out[r.y], v.y * x1);
    atomicAdd(&out[r.z], v.z * x2);
    atomicAdd(&out[r.w], v.w * x3);
}

// Tail handler for nnz not divisible by 4 (host-guarded out for this shape).
__global__ void coo_spmv_tail_kernel(
    const float* __restrict__ x,
    const float* __restrict__ vals,
    const int*   __restrict__ rows,
    const int*   __restrict__ cols,
    float*       __restrict__ out,
    int start, int nnz)
{
    int i = start + blockIdx.x * blockDim.x + threadIdx.x;
    if (i < nnz) {
        atomicAdd(&out[rows[i]], vals[i] * __ldg(&x[cols[i]]));
    }
}

extern "C" void kernel_launch(void* const* d_in, const int* in_sizes, int n_in,
                              void* d_out, int out_size) {
    const float* x    = (const float*)d_in[0];
    const float* vals = (const float*)d_in[1];
    const int*   rows = (const int*)d_in[2];
    const int*   cols = (const int*)d_in[3];
    float* out = (float*)d_out;

    const int nnz = in_sizes[1];

    // Zero-init output (harness poisons it to 0xAA).
    {
        int n4 = out_size / 4;               // out_size divisible by 4 here
        zero_out_kernel<<<(n4 + 255) / 256, 256>>>((float4*)out, n4);
    }

    // Main vectorized COO pass: 4 nnz per thread (best-measured shape).
    int nnz4 = nnz / 4;
    if (nnz4 > 0) {
        int threads = 256;
        int blocks = (nnz4 + threads - 1) / threads;
        coo_spmv_kernel<<<blocks, threads>>>(
            x, (const float4*)vals, (const int4*)rows, (const int4*)cols, out, nnz4);
    }

    // Tail (nnz % 4): empty for this shape -> no node enters the graph.
    int tail_start = nnz4 * 4;
    int tail = nnz - tail_start;
    if (tail > 0) {
        coo_spmv_tail_kernel<<<(tail + 255) / 256, 256>>>(
            x, vals, rows, cols, out, tail_start, nnz);
    }
}